// round 1
// baseline (speedup 1.0000x reference)
#include <cuda_runtime.h>
#include <math.h>

// Problem constants (fixed by setup_inputs)
#define BB   32
#define AA   3
#define HH   64
#define WW   64
#define CC   80
#define PRED_LAST 85          // 5 + C
#define NT   2048
#define CELLS (BB*AA*HH*WW)   // 393216

// Scratch: zero-initialized device globals. Every kernel that consumes them
// resets them back to zero in the same pass, so each kernel_launch call sees
// the identical initial state (graph-replay safe, deterministic).
__device__ unsigned char g_obj[CELLS];   // obj mask
__device__ unsigned char g_kz[CELLS];    // "keep product is zero" sticky flag
__device__ double g_acc[5];              // 0:conf_sum 1:n_obj 2:n_noobj 3:xywh_sum 4:cls_sum

__device__ __forceinline__ float softplusf(float x) {
    // max(x,0) + log1p(exp(-|x|))  == bce(x, t=0)
    return fmaxf(x, 0.0f) + log1pf(expf(-fabsf(x)));
}

// ---------------------------------------------------------------------------
// Kernel 1: one block per target.
//   thread 0: IoU argmax, mask scatter, xywh MSE contribution
//   all threads: cls BCE over the gathered 80-float row (coalesced)
// ---------------------------------------------------------------------------
__global__ void k_targets(const float* __restrict__ pred,
                          const float* __restrict__ target,
                          const float* __restrict__ anchors)
{
    const int n   = blockIdx.x;
    const int tid = threadIdx.x;

    const float* t = target + n * 6;
    const float tb = t[0], tl = t[1];
    const float tx = t[2] * (float)HH;
    const float ty = t[3] * (float)HH;
    const float tw = t[4] * (float)HH;
    const float th = t[5] * (float)HH;

    const int b   = (int)tb;
    const int lab = (int)tl;
    const int wi  = (int)tw;   // NOTE: grid indices come from WH in the reference
    const int hi  = (int)th;

    // IoU vs each anchor; argmax with first-max tie-break (strict >)
    float ious[AA];
    float best = -1.0f;
    int   besta = 0;
    #pragma unroll
    for (int a = 0; a < AA; ++a) {
        const float aw = anchors[2*a], ah = anchors[2*a + 1];
        const float inter = fminf(aw, tw) * fminf(ah, th);
        const float iou = inter / (aw*ah + tw*th - inter);
        ious[a] = iou;
        if (iou > best) { best = iou; besta = a; }
    }

    const long long cell_best = ((long long)(b*AA + besta)*HH + hi)*WW + wi;

    if (tid == 0) {
        #pragma unroll
        for (int a = 0; a < AA; ++a) {
            if (ious[a] > 0.5f) {
                const long long ci = ((long long)(b*AA + a)*HH + hi)*WW + wi;
                g_kz[ci] = 1;   // keep==0 -> noobj multiplied to zero
            }
        }
        g_obj[cell_best] = 1;

        // xywh MSE contribution
        const float* p = pred + cell_best * PRED_LAST;
        const float fx = tx - floorf(tx);
        const float fy = ty - floorf(ty);
        const float lw = logf(tw / anchors[2*besta]);
        const float lh = logf(th / anchors[2*besta + 1]);
        const float d0 = p[0] - fx, d1 = p[1] - fy;
        const float d2 = p[2] - lw, d3 = p[3] - lh;
        atomicAdd(&g_acc[3], (double)(d0*d0 + d1*d1 + d2*d2 + d3*d3));
    }

    // cls BCE over one-hot target: bce(x, t) = softplus-ish, minus x when c==label
    const float* pcls = pred + cell_best * PRED_LAST + 5;
    float s = 0.0f;
    for (int c = tid; c < CC; c += blockDim.x) {
        const float x = pcls[c];
        float v = softplusf(x);
        if (c == lab) v -= x;
        s += v;
    }

    __shared__ float sh[128];
    sh[tid] = s;
    __syncthreads();
    #pragma unroll
    for (int o = 64; o > 0; o >>= 1) {
        if (tid < o) sh[tid] += sh[tid + o];
        __syncthreads();
    }
    if (tid == 0) atomicAdd(&g_acc[4], (double)sh[0]);
}

// ---------------------------------------------------------------------------
// Kernel 2: full-grid conf term. One thread per cell; strided pick of
// pred[...,4] (unique 32B sector per load => ~12.6MB traffic, not 133MB).
// Reads + resets the masks in the same pass.
// ---------------------------------------------------------------------------
__global__ void k_conf(const float* __restrict__ pred)
{
    const int i = blockIdx.x * blockDim.x + threadIdx.x;

    float conf = 0.0f;
    int   n_o  = 0;
    int   n_n  = 0;

    if (i < CELLS) {
        const float pc = __ldg(pred + (long long)i * PRED_LAST + 4);
        const unsigned char o  = g_obj[i];
        const unsigned char kz = g_kz[i];
        if (o | kz) { g_obj[i] = 0; g_kz[i] = 0; }   // reset only touched cells

        const float sp = softplusf(pc);
        if (o)        { conf = sp - pc; n_o = 1; }   // bce(pc, 1)
        else if (!kz) { conf = sp;      n_n = 1; }   // bce(pc, 0) * noobj
    }

    __shared__ float sconf[256];
    __shared__ int   scnt[256];
    const int tid = threadIdx.x;
    sconf[tid] = conf;
    scnt[tid]  = (n_o << 16) | n_n;
    __syncthreads();
    #pragma unroll
    for (int o = 128; o > 0; o >>= 1) {
        if (tid < o) { sconf[tid] += sconf[tid + o]; scnt[tid] += scnt[tid + o]; }
        __syncthreads();
    }
    if (tid == 0) {
        atomicAdd(&g_acc[0], (double)sconf[0]);
        atomicAdd(&g_acc[1], (double)(scnt[0] >> 16));
        atomicAdd(&g_acc[2], (double)(scnt[0] & 0xFFFF));
    }
}

// ---------------------------------------------------------------------------
// Kernel 3: finalize + reset accumulators for the next replay.
// ---------------------------------------------------------------------------
__global__ void k_final(float* __restrict__ out)
{
    const double conf = g_acc[0];
    const double nobj = g_acc[1];
    const double nno  = g_acc[2];
    const double xywh = g_acc[3];
    const double cls  = g_acc[4];

    const double loss = xywh / ((double)NT * 4.0)
                      + conf / (nobj + nno)
                      + cls  / ((double)NT * (double)CC);
    out[0] = (float)loss;

    g_acc[0] = 0.0; g_acc[1] = 0.0; g_acc[2] = 0.0; g_acc[3] = 0.0; g_acc[4] = 0.0;
}

extern "C" void kernel_launch(void* const* d_in, const int* in_sizes, int n_in,
                              void* d_out, int out_size)
{
    const float* pred    = (const float*)d_in[0];
    const float* target  = (const float*)d_in[1];
    const float* anchors = (const float*)d_in[2];
    float* out = (float*)d_out;

    k_targets<<<NT, 128>>>(pred, target, anchors);
    k_conf<<<CELLS / 256, 256>>>(pred);
    k_final<<<1, 1>>>(out);
}

// round 2
// speedup vs baseline: 1.8200x; 1.8200x over previous
#include <cuda_runtime.h>
#include <math.h>

// Problem constants (fixed by setup_inputs)
#define BB   32
#define AA   3
#define HH   64
#define WW   64
#define CC   80
#define PRED_LAST 85          // 5 + C
#define NT   2048
#define CELLS (BB*AA*HH*WW)   // 393216

#define CONF_THREADS 256
#define CONF_BLOCKS  192      // 49152 threads * 8 cells = 393216

// Scratch: zero-initialized device globals. Each kernel that consumes them
// resets them in the same pass (graph-replay safe, deterministic).
__device__ unsigned char g_obj[CELLS];       // obj mask
__device__ unsigned char g_kz[CELLS];        // "keep product is zero" sticky flag
__device__ double g_acc[4];                  // 0:conf 1:xywh 2:cls (3 unused)
__device__ unsigned long long g_cnt;         // (n_obj<<32) | n_noobj

__device__ __forceinline__ float softplusf(float x) {
    return fmaxf(x, 0.0f) + log1pf(expf(-fabsf(x)));
}

__device__ __forceinline__ float warp_sum(float v) {
    #pragma unroll
    for (int o = 16; o > 0; o >>= 1) v += __shfl_down_sync(0xFFFFFFFFu, v, o);
    return v;
}

// ---------------------------------------------------------------------------
// Kernel 1: one WARP per target; 8 targets per 256-thread block.
// ---------------------------------------------------------------------------
__global__ void k_targets(const float* __restrict__ pred,
                          const float* __restrict__ target,
                          const float* __restrict__ anchors)
{
    const int tid  = threadIdx.x;
    const int lane = tid & 31;
    const int wrp  = tid >> 5;
    const int n    = blockIdx.x * 8 + wrp;

    const float* t = target + n * 6;
    const float tb = __ldg(t + 0);
    const float tl = __ldg(t + 1);
    const float tx = __ldg(t + 2) * (float)HH;
    const float ty = __ldg(t + 3) * (float)HH;
    const float tw = __ldg(t + 4) * (float)HH;
    const float th = __ldg(t + 5) * (float)HH;

    const int b   = (int)tb;
    const int lab = (int)tl;
    const int wi  = (int)tw;   // grid indices come from WH in the reference
    const int hi  = (int)th;

    // IoU vs 3 anchors; argmax with first-max tie-break (strict >)
    float ious[AA];
    float best = -1.0f;
    int   besta = 0;
    #pragma unroll
    for (int a = 0; a < AA; ++a) {
        const float aw = __ldg(anchors + 2*a), ah = __ldg(anchors + 2*a + 1);
        const float inter = fminf(aw, tw) * fminf(ah, th);
        const float iou = inter / (aw*ah + tw*th - inter);
        ious[a] = iou;
        if (iou > best) { best = iou; besta = a; }
    }

    const int cell_best = ((b*AA + besta)*HH + hi)*WW + wi;
    const float* prow = pred + (long long)cell_best * PRED_LAST;

    float xywh = 0.0f;
    if (lane == 0) {
        #pragma unroll
        for (int a = 0; a < AA; ++a) {
            if (ious[a] > 0.5f) g_kz[((b*AA + a)*HH + hi)*WW + wi] = 1;
        }
        g_obj[cell_best] = 1;

        const float fx = tx - floorf(tx);
        const float fy = ty - floorf(ty);
        const float lw = logf(tw / __ldg(anchors + 2*besta));
        const float lh = logf(th / __ldg(anchors + 2*besta + 1));
        const float d0 = prow[0] - fx, d1 = prow[1] - fy;
        const float d2 = prow[2] - lw, d3 = prow[3] - lh;
        xywh = d0*d0 + d1*d1 + d2*d2 + d3*d3;
    }

    // cls BCE over one-hot: 80 channels -> lanes handle c, c+32, c+64
    const float* pcls = prow + 5;
    const float x0 = __ldg(pcls + lane);
    const float x1 = __ldg(pcls + lane + 32);
    const float x2 = (lane < 16) ? __ldg(pcls + lane + 64) : 0.0f;

    float s = softplusf(x0) + softplusf(x1);
    if (lane < 16) s += softplusf(x2);
    // subtract x at the label channel
    if (lane == (lab & 31) && (lab >> 5) == 0) s -= x0;
    if (lane == (lab - 32)) s -= x1;
    if (lane == (lab - 64)) s -= x2;

    s = warp_sum(s);   // lane 0 holds warp cls sum

    __shared__ float scl[8];
    __shared__ float sxy[8];
    if (lane == 0) { scl[wrp] = s; sxy[wrp] = xywh; }
    __syncthreads();
    if (tid == 0) {
        float cs = 0.0f, xs = 0.0f;
        #pragma unroll
        for (int w = 0; w < 8; ++w) { cs += scl[w]; xs += sxy[w]; }
        atomicAdd(&g_acc[2], (double)cs);
        atomicAdd(&g_acc[1], (double)xs);
    }
}

// ---------------------------------------------------------------------------
// Kernel 2: full-grid conf term, 8 cells per thread (batched loads => MLP=8).
// Reads + resets the masks in the same pass.
// ---------------------------------------------------------------------------
__global__ void __launch_bounds__(CONF_THREADS) k_conf(const float* __restrict__ pred)
{
    const int base   = blockIdx.x * CONF_THREADS + threadIdx.x;
    const int stride = CONF_BLOCKS * CONF_THREADS;   // 49152

    float pc[8];
    unsigned char o[8], kz[8];
    #pragma unroll
    for (int k = 0; k < 8; ++k) {
        const int c = base + k * stride;
        pc[k] = __ldg(pred + c * PRED_LAST + 4);
    }
    #pragma unroll
    for (int k = 0; k < 8; ++k) {
        const int c = base + k * stride;
        o[k]  = g_obj[c];
        kz[k] = g_kz[c];
    }

    float conf = 0.0f;
    int n_o = 0, n_n = 0;
    #pragma unroll
    for (int k = 0; k < 8; ++k) {
        const int c = base + k * stride;
        if (o[k] | kz[k]) { g_obj[c] = 0; g_kz[c] = 0; }   // reset touched cells
        const float sp = softplusf(pc[k]);
        if (o[k])        { conf += sp - pc[k]; n_o++; }     // bce(pc, 1)
        else if (!kz[k]) { conf += sp;         n_n++; }     // bce(pc, 0)
    }

    // block reduction: warp shuffle -> smem -> one atomic pair per block
    conf = warp_sum(conf);
    int cnt = (n_o << 16) | n_n;
    #pragma unroll
    for (int off = 16; off > 0; off >>= 1) cnt += __shfl_down_sync(0xFFFFFFFFu, cnt, off);

    __shared__ float sc[8];
    __shared__ int   si[8];
    const int lane = threadIdx.x & 31, wrp = threadIdx.x >> 5;
    if (lane == 0) { sc[wrp] = conf; si[wrp] = cnt; }
    __syncthreads();
    if (threadIdx.x == 0) {
        float cs = 0.0f; int ci = 0;
        #pragma unroll
        for (int w = 0; w < 8; ++w) { cs += sc[w]; ci += si[w]; }
        atomicAdd(&g_acc[0], (double)cs);
        const unsigned long long packed =
            ((unsigned long long)(unsigned)(ci >> 16) << 32) |
            (unsigned long long)(unsigned)(ci & 0xFFFF);
        atomicAdd(&g_cnt, packed);
    }
}

// ---------------------------------------------------------------------------
// Kernel 3: finalize + reset accumulators for the next replay.
// ---------------------------------------------------------------------------
__global__ void k_final(float* __restrict__ out)
{
    const double conf = g_acc[0];
    const double xywh = g_acc[1];
    const double cls  = g_acc[2];
    const unsigned long long cnt = g_cnt;
    const double n_obj   = (double)(cnt >> 32);
    const double n_noobj = (double)(cnt & 0xFFFFFFFFull);

    const double loss = xywh / ((double)NT * 4.0)
                      + conf / (n_obj + n_noobj)
                      + cls  / ((double)NT * (double)CC);
    out[0] = (float)loss;

    g_acc[0] = 0.0; g_acc[1] = 0.0; g_acc[2] = 0.0;
    g_cnt = 0ull;
}

extern "C" void kernel_launch(void* const* d_in, const int* in_sizes, int n_in,
                              void* d_out, int out_size)
{
    const float* pred    = (const float*)d_in[0];
    const float* target  = (const float*)d_in[1];
    const float* anchors = (const float*)d_in[2];
    float* out = (float*)d_out;

    k_targets<<<NT / 8, 256>>>(pred, target, anchors);
    k_conf<<<CONF_BLOCKS, CONF_THREADS>>>(pred);
    k_final<<<1, 1>>>(out);
}